// round 13
// baseline (speedup 1.0000x reference)
#include <cuda_runtime.h>
#include <cuda_bf16.h>
#include <math.h>
#include <cstdint>

#define BATCH 32
#define NTOK  3136
#define DIM   384
#define HEADS 8
#define CH    48
#define MTOT  (BATCH * NTOK)   // 100352
#define ETOT  (3 * DIM)        // 1152
#define KD    384

typedef __nv_bfloat16 bf16;

// Scratch (__device__ globals)
__device__ bf16  g_xh [(size_t)MTOT * KD];
__device__ bf16  g_xl [(size_t)MTOT * KD];
__device__ bf16  g_wqh[(size_t)ETOT * KD];
__device__ bf16  g_wql[(size_t)ETOT * KD];
__device__ bf16  g_qkh[((size_t)2 * DIM + 16) * MTOT];       // q,k bf16-high [e][m] (+pad rows)
__device__ bf16  g_qkl[((size_t)2 * DIM + 16) * MTOT];       // low
__device__ bf16  g_vth[((size_t)MTOT + 128) * KD];           // v^T [m][d] high
__device__ bf16  g_vtl[((size_t)MTOT + 128) * KD];           // low
__device__ bf16  g_wh [(size_t)BATCH * DIM * DIM];           // W_b = P·S  [b][f][d] high
__device__ bf16  g_wl [(size_t)BATCH * DIM * DIM];
__device__ float g_ps [512 * 48 * 48];                       // partial S
__device__ float g_pn [512 * 96];                            // partial sq-norms

// ---------------------------------------------------------------------------
__device__ __forceinline__ uint32_t smem_u32(const void* p) {
    uint32_t a;
    asm("{ .reg .u64 t; cvta.to.shared.u64 t, %1; cvt.u32.u64 %0, t; }" : "=r"(a) : "l"(p));
    return a;
}
__device__ __forceinline__ void bsplit2(float x0, float x1, uint32_t& h, uint32_t& l) {
    __nv_bfloat16 h0 = __float2bfloat16(x0);
    __nv_bfloat16 h1 = __float2bfloat16(x1);
    __nv_bfloat16 l0 = __float2bfloat16(x0 - __bfloat162float(h0));
    __nv_bfloat16 l1 = __float2bfloat16(x1 - __bfloat162float(h1));
    __nv_bfloat162 hv = __halves2bfloat162(h0, h1);
    __nv_bfloat162 lv = __halves2bfloat162(l0, l1);
    h = *reinterpret_cast<uint32_t*>(&hv);
    l = *reinterpret_cast<uint32_t*>(&lv);
}
__device__ __forceinline__ void cp16(uint32_t d, const void* s) {
    asm volatile("cp.async.cg.shared.global [%0], [%1], 16;" :: "r"(d), "l"(s));
}
__device__ __forceinline__ void cp_commit() { asm volatile("cp.async.commit_group;"); }

#define LDSM4(r0, r1, r2, r3, addr) \
    asm volatile("ldmatrix.sync.aligned.m8n8.x4.shared.b16 {%0,%1,%2,%3}, [%4];" \
        : "=r"(r0), "=r"(r1), "=r"(r2), "=r"(r3) : "r"(addr))

#define MMA_BF16(d, A0,A1,A2,A3, B0,B1) \
    asm volatile("mma.sync.aligned.m16n8k16.row.col.f32.bf16.bf16.f32 " \
        "{%0,%1,%2,%3}, {%4,%5,%6,%7}, {%8,%9}, {%0,%1,%2,%3};" \
        : "+f"((d)[0]), "+f"((d)[1]), "+f"((d)[2]), "+f"((d)[3]) \
        : "r"(A0), "r"(A1), "r"(A2), "r"(A3), "r"(B0), "r"(B1))

// ---------------------------------------------------------------------------
// Shared 128x128 GEMM machinery (K=384 in 12 chunks of 32)
// ---------------------------------------------------------------------------
#define BST     40
#define TILE_B  (128 * BST * 2)
#define STAGE_B (4 * TILE_B)
#define GSMEM   (2 * STAGE_B)

__device__ __forceinline__ void load_stage(
    uint32_t sb, const bf16* Ah, const bf16* Al,
    const bf16* Bh, const bf16* Bl, int k0, int tid)
{
    const int row = tid >> 1;
    const int s2  = (tid & 1) * 2;
    const uint32_t ro = row * 80 + s2 * 16;
    const size_t go = (size_t)row * KD + k0 + s2 * 8;
    cp16(sb + ro,            Ah + go);  cp16(sb + ro + 16,            Ah + go + 8);
    cp16(sb + TILE_B + ro,   Al + go);  cp16(sb + TILE_B + ro + 16,   Al + go + 8);
    cp16(sb + 2*TILE_B + ro, Bh + go);  cp16(sb + 2*TILE_B + ro + 16, Bh + go + 8);
    cp16(sb + 3*TILE_B + ro, Bl + go);  cp16(sb + 3*TILE_B + ro + 16, Bl + go + 8);
}

__device__ __forceinline__ void mma_stage(
    uint32_t sb, int wm, int wn, int lane, float acc[4][4][4])
{
    const int j  = lane >> 3;
    const int rr = lane & 7;
#pragma unroll
    for (int kk = 0; kk < 32; kk += 16) {
        uint32_t bh[4][2], bl[4][2];
#pragma unroll
        for (int p = 0; p < 2; p++) {
            uint32_t off = (uint32_t)(((wn + (2*p + (j >> 1)) * 8 + rr) * BST + kk + (j & 1) * 8) * 2);
            LDSM4(bh[2*p][0], bh[2*p][1], bh[2*p+1][0], bh[2*p+1][1], sb + 2*TILE_B + off);
            LDSM4(bl[2*p][0], bl[2*p][1], bl[2*p+1][0], bl[2*p+1][1], sb + 3*TILE_B + off);
        }
#pragma unroll
        for (int mt = 0; mt < 4; mt++) {
            uint32_t aoff = (uint32_t)(((wm + mt*16 + (j & 1) * 8 + rr) * BST + kk + (j >> 1) * 8) * 2);
            uint32_t a0r, a1r, a2r, a3r, l0r, l1r, l2r, l3r;
            LDSM4(a0r, a1r, a2r, a3r, sb + aoff);
            LDSM4(l0r, l1r, l2r, l3r, sb + TILE_B + aoff);
#pragma unroll
            for (int nt = 0; nt < 4; nt++) {
                MMA_BF16(acc[mt][nt], a0r, a1r, a2r, a3r, bh[nt][0], bh[nt][1]);
                MMA_BF16(acc[mt][nt], l0r, l1r, l2r, l3r, bh[nt][0], bh[nt][1]);
                MMA_BF16(acc[mt][nt], a0r, a1r, a2r, a3r, bl[nt][0], bl[nt][1]);
            }
        }
    }
}

__device__ __forceinline__ void gemm_mainloop(
    uint32_t sbase, const bf16* Ah, const bf16* Al,
    const bf16* Bh, const bf16* Bl,
    int wm, int wn, int lane, int tid, float acc[4][4][4])
{
    load_stage(sbase, Ah, Al, Bh, Bl, 0, tid);
    cp_commit();
    for (int c = 0; c < 12; c++) {
        if (c < 11) {
            load_stage(sbase + ((c + 1) & 1) * STAGE_B, Ah, Al, Bh, Bl, (c + 1) * 32, tid);
            cp_commit();
            asm volatile("cp.async.wait_group 1;");
        } else {
            asm volatile("cp.async.wait_group 0;");
        }
        __syncthreads();
        mma_stage(sbase + (c & 1) * STAGE_B, wm, wn, lane, acc);
        __syncthreads();
    }
}

// ---------------------------------------------------------------------------
// Prepass: fp32 -> bf16 h/l split
// ---------------------------------------------------------------------------
__global__ void __launch_bounds__(256) split_kernel(
    const float4* __restrict__ src, uint2* __restrict__ dh, uint2* __restrict__ dl, int n4)
{
    int i = blockIdx.x * 256 + threadIdx.x;
    if (i >= n4) return;
    float4 v = src[i];
    uint32_t h0, l0, h1, l1;
    bsplit2(v.x, v.y, h0, l0);
    bsplit2(v.z, v.w, h1, l1);
    dh[i] = make_uint2(h0, h1);
    dl[i] = make_uint2(l0, l1);
}

// ---------------------------------------------------------------------------
// G1: qkv GEMM. grid.x = e-tile (9, fastest -> x-tile L2 reuse), grid.y = m-tile.
// q/k -> bf16 h/l [e][m]; v -> transposed bf16 h/l [m][d].
// ---------------------------------------------------------------------------
__global__ void __launch_bounds__(256, 2) gemm_qkv_kernel()
{
    extern __shared__ char sb[];
    const uint32_t sbase = smem_u32(sb);
    const int tid  = threadIdx.x;
    const int wid  = tid >> 5;
    const int lane = tid & 31;
    const int g = lane >> 2, t = lane & 3;
    const int a0 = blockIdx.x * 128;   // e  (fastest -> 9 CTAs share x tile)
    const int b0 = blockIdx.y * 128;   // m
    const int wm = (wid >> 2) * 64, wn = (wid & 3) * 32;

    float acc[4][4][4];
#pragma unroll
    for (int mt = 0; mt < 4; mt++)
#pragma unroll
        for (int nt = 0; nt < 4; nt++)
#pragma unroll
            for (int i = 0; i < 4; i++) acc[mt][nt][i] = 0.f;

    gemm_mainloop(sbase,
                  g_wqh + (size_t)a0 * KD, g_wql + (size_t)a0 * KD,
                  g_xh  + (size_t)b0 * KD, g_xl  + (size_t)b0 * KD,
                  wm, wn, lane, tid, acc);

    if (a0 < 2 * DIM) {
        // q/k: bf16 h/l [e][m]
#pragma unroll
        for (int mt = 0; mt < 4; mt++) {
            int row = a0 + wm + mt * 16 + g;
#pragma unroll
            for (int nt = 0; nt < 4; nt++) {
                int col = b0 + wn + nt * 8 + 2 * t;
                uint32_t hw, lw;
                bsplit2(acc[mt][nt][0], acc[mt][nt][1], hw, lw);
                *(uint32_t*)(g_qkh + (size_t)row * MTOT + col) = hw;
                *(uint32_t*)(g_qkl + (size_t)row * MTOT + col) = lw;
                bsplit2(acc[mt][nt][2], acc[mt][nt][3], hw, lw);
                *(uint32_t*)(g_qkh + (size_t)(row + 8) * MTOT + col) = hw;
                *(uint32_t*)(g_qkl + (size_t)(row + 8) * MTOT + col) = lw;
            }
        }
    } else {
        // v: transpose-stage then split to [m][d]
        float* smf = (float*)sb;  // [128 m][132 e]
#pragma unroll
        for (int mt = 0; mt < 4; mt++) {
            int er = wm + mt * 16 + g;
#pragma unroll
            for (int nt = 0; nt < 4; nt++) {
                int mc = wn + nt * 8 + 2 * t;
                smf[mc * 132 + er]           = acc[mt][nt][0];
                smf[(mc + 1) * 132 + er]     = acc[mt][nt][1];
                smf[mc * 132 + er + 8]       = acc[mt][nt][2];
                smf[(mc + 1) * 132 + er + 8] = acc[mt][nt][3];
            }
        }
        __syncthreads();
        const int mrow = tid >> 1, hf = tid & 1;
        const int dv0 = a0 - 2 * DIM;
        const float* srow = smf + mrow * 132 + hf * 64;
        uint32_t* th = (uint32_t*)(g_vth + (size_t)(b0 + mrow) * KD + dv0 + hf * 64);
        uint32_t* tl = (uint32_t*)(g_vtl + (size_t)(b0 + mrow) * KD + dv0 + hf * 64);
#pragma unroll
        for (int jj = 0; jj < 32; jj++) {
            uint32_t hw, lw;
            bsplit2(srow[2 * jj], srow[2 * jj + 1], hw, lw);
            th[jj] = hw;
            tl[jj] = lw;
        }
    }
}

// ---------------------------------------------------------------------------
// G2: proj GEMM per batch
// ---------------------------------------------------------------------------
__global__ void __launch_bounds__(256, 2) gemm_proj_kernel(
    const float* __restrict__ bias, float* __restrict__ out)
{
    extern __shared__ char sb[];
    const uint32_t sbase = smem_u32(sb);
    const int tid  = threadIdx.x;
    const int wid  = tid >> 5;
    const int lane = tid & 31;
    const int g = lane >> 2, t = lane & 3;
    const int f0 = blockIdx.x * 128;
    const int n0 = blockIdx.y * 128;
    const int b  = blockIdx.z;
    const int wm = (wid >> 2) * 64, wn = (wid & 3) * 32;
    const size_t vrow0 = (size_t)b * NTOK + n0;
    const size_t wrow0 = (size_t)b * DIM + f0;
    const int nlim = NTOK - n0;

    float acc[4][4][4];
#pragma unroll
    for (int mt = 0; mt < 4; mt++)
#pragma unroll
        for (int nt = 0; nt < 4; nt++)
#pragma unroll
            for (int i = 0; i < 4; i++) acc[mt][nt][i] = 0.f;

    gemm_mainloop(sbase,
                  g_vth + vrow0 * KD, g_vtl + vrow0 * KD,
                  g_wh  + wrow0 * KD, g_wl  + wrow0 * KD,
                  wm, wn, lane, tid, acc);

#pragma unroll
    for (int mt = 0; mt < 4; mt++) {
        int nrow = wm + mt * 16 + g;
#pragma unroll
        for (int nt = 0; nt < 4; nt++) {
            int col = f0 + wn + nt * 8 + 2 * t;
            float bv0 = bias[col], bv1 = bias[col + 1];
            if (nrow < nlim)
                *(float2*)(out + ((size_t)b * NTOK + n0 + nrow) * DIM + col) =
                    make_float2(acc[mt][nt][0] + bv0, acc[mt][nt][1] + bv1);
            if (nrow + 8 < nlim)
                *(float2*)(out + ((size_t)b * NTOK + n0 + nrow + 8) * DIM + col) =
                    make_float2(acc[mt][nt][2] + bv0, acc[mt][nt][3] + bv1);
        }
    }
}

// ---------------------------------------------------------------------------
// attn partial: per (b,h,half) tensor-core S(48x48 in 64x64) + sq-norms.
// A = q rows (bf16 h/l), B = k rows; contraction over 1568 tokens, 49 chunks of 32.
// ---------------------------------------------------------------------------
#define APLANE 5120                   // 64 rows * 80 B
#define ASTAGE (4 * APLANE)           // qh | ql | kh | kl
#define ASMEM  (2 * ASTAGE)           // 40960

__global__ void __launch_bounds__(256, 2) attn_mma_kernel()
{
    extern __shared__ char sb[];
    const uint32_t sbase = smem_u32(sb);
    const int blk = blockIdx.x;           // 0..511
    const int bh = blk >> 1, half = blk & 1;
    const int b = bh >> 3, h = bh & 7;
    const int tid  = threadIdx.x;
    const int wid  = tid >> 5;
    const int lane = tid & 31;
    const int g = lane >> 2, t = lane & 3;
    const int j = lane >> 3, rr = lane & 7;
    const int wm = (wid >> 1) * 16;       // 0,16,32,48
    const int wn = (wid & 1) * 32;

    const size_t bcol = (size_t)b * NTOK + half * 1568;
    const size_t qoff = (size_t)(h * CH) * MTOT + bcol;
    const size_t koff = (size_t)(DIM + h * CH) * MTOT + bcol;

    const int lrow = tid & 63;
    const int pl   = tid >> 6;
    const bf16* myrow;
    {
        const bf16* bases[4] = { g_qkh + qoff, g_qkl + qoff, g_qkh + koff, g_qkl + koff };
        myrow = bases[pl] + (size_t)lrow * MTOT;
    }

    float acc[4][4];
#pragma unroll
    for (int nt = 0; nt < 4; nt++)
#pragma unroll
        for (int i = 0; i < 4; i++) acc[nt][i] = 0.f;
    float nacc = 0.f;

    // loader: 4x cp16 per thread per chunk
    // norm reader coords
    const int nr_row = (tid < 48) ? tid : tid - 48;
    const int nr_pl  = (tid < 48) ? 0 : 2;          // qh or kh plane index

    {
        const uint32_t d0 = sbase + pl * APLANE + lrow * 80;
        const bf16* s0 = myrow;
        cp16(d0, s0); cp16(d0 + 16, s0 + 8); cp16(d0 + 32, s0 + 16); cp16(d0 + 48, s0 + 24);
        cp_commit();
    }
    for (int c = 0; c < 49; c++) {
        if (c < 48) {
            const uint32_t d0 = sbase + ((c + 1) & 1) * ASTAGE + pl * APLANE + lrow * 80;
            const bf16* s0 = myrow + (c + 1) * 32;
            cp16(d0, s0); cp16(d0 + 16, s0 + 8); cp16(d0 + 32, s0 + 16); cp16(d0 + 48, s0 + 24);
            cp_commit();
            asm volatile("cp.async.wait_group 1;");
        } else {
            asm volatile("cp.async.wait_group 0;");
        }
        __syncthreads();
        const uint32_t ss = sbase + (c & 1) * ASTAGE;
        // norms (threads 0..95) from h+l planes
        if (tid < 96) {
            const char* ph = sb + (c & 1) * ASTAGE + nr_pl * APLANE + nr_row * 80;
            const char* plo = ph + APLANE;
#pragma unroll
            for (int i = 0; i < 16; i++) {
                __nv_bfloat162 hv = *(const __nv_bfloat162*)(ph + 4 * i);
                __nv_bfloat162 lv = *(const __nv_bfloat162*)(plo + 4 * i);
                float2 hf = __bfloat1622float2(hv);
                float2 lf = __bfloat1622float2(lv);
                float v0 = hf.x + lf.x, v1 = hf.y + lf.y;
                nacc += v0 * v0 + v1 * v1;
            }
        }
#pragma unroll
        for (int kk = 0; kk < 32; kk += 16) {
            uint32_t bh2[4][2], bl2[4][2];
#pragma unroll
            for (int p = 0; p < 2; p++) {
                uint32_t off = (uint32_t)(((wn + (2*p + (j >> 1)) * 8 + rr) * 40 + kk + (j & 1) * 8) * 2);
                LDSM4(bh2[2*p][0], bh2[2*p][1], bh2[2*p+1][0], bh2[2*p+1][1], ss + 2*APLANE + off);
                LDSM4(bl2[2*p][0], bl2[2*p][1], bl2[2*p+1][0], bl2[2*p+1][1], ss + 3*APLANE + off);
            }
            uint32_t aoff = (uint32_t)(((wm + (j & 1) * 8 + rr) * 40 + kk + (j >> 1) * 8) * 2);
            uint32_t a0r, a1r, a2r, a3r, l0r, l1r, l2r, l3r;
            LDSM4(a0r, a1r, a2r, a3r, ss + aoff);
            LDSM4(l0r, l1r, l2r, l3r, ss + APLANE + aoff);
#pragma unroll
            for (int nt = 0; nt < 4; nt++) {
                MMA_BF16(acc[nt], a0r, a1r, a2r, a3r, bh2[nt][0], bh2[nt][1]);
                MMA_BF16(acc[nt], l0r, l1r, l2r, l3r, bh2[nt][0], bh2[nt][1]);
                MMA_BF16(acc[nt], a0r, a1r, a2r, a3r, bl2[nt][0], bl2[nt][1]);
            }
        }
        __syncthreads();
    }

    // store partials (valid 48x48 region only)
    float* ps = g_ps + (size_t)blk * 2304;
    const int c0 = wm + g;
#pragma unroll
    for (int nt = 0; nt < 4; nt++) {
        int d0 = wn + nt * 8 + 2 * t;
        if (d0 < 48) {
            if (c0 < 48) {
                ps[c0 * 48 + d0]     = acc[nt][0];
                ps[c0 * 48 + d0 + 1] = acc[nt][1];
            }
            if (c0 + 8 < 48) {
                ps[(c0 + 8) * 48 + d0]     = acc[nt][2];
                ps[(c0 + 8) * 48 + d0 + 1] = acc[nt][3];
            }
        }
    }
    if (tid < 96) g_pn[blk * 96 + tid] = nacc;
}

// ---------------------------------------------------------------------------
// attn combine: sum partials, normalize, temp, softmax, W_b = P·S -> bf16 split
// ---------------------------------------------------------------------------
__global__ void __launch_bounds__(256) attn_combine_kernel(
    const float* __restrict__ temperature, const float* __restrict__ projw)
{
    __shared__ float S[48 * 52];
    __shared__ float norms[96];

    const int bh = blockIdx.x;
    const int b = bh >> 3, h = bh & 7;
    const int tid = threadIdx.x;

    const float* ps0 = g_ps + (size_t)(bh * 2) * 2304;
    const float* ps1 = ps0 + 2304;
    for (int c = tid; c < 2304; c += 256)
        S[(c / 48) * 52 + (c % 48)] = ps0[c] + ps1[c];
    if (tid < 96) {
        float n = g_pn[(bh * 2) * 96 + tid] + g_pn[(bh * 2 + 1) * 96 + tid];
        norms[tid] = 1.f / fmaxf(sqrtf(n), 1e-12f);
    }
    __syncthreads();

    const float temp = temperature[h];
    for (int c = tid; c < 2304; c += 256) {
        int i = c / 48, jj = c % 48;
        S[i * 52 + jj] *= norms[i] * norms[48 + jj] * temp;
    }
    __syncthreads();

    if (tid < CH) {
        float* row = S + tid * 52;
        float mx = -1e30f;
#pragma unroll
        for (int d = 0; d < CH; d++) mx = fmaxf(mx, row[d]);
        float s = 0.f;
#pragma unroll
        for (int d = 0; d < CH; d++) { float e = expf(row[d] - mx); row[d] = e; s += e; }
        float inv = 1.f / s;
#pragma unroll
        for (int d = 0; d < CH; d++) row[d] *= inv;
    }
    __syncthreads();

    const int fl = tid >> 1;
    const int dh = (tid & 1) * 24;
    for (int rep = 0; rep < 3; rep++) {
        int f = fl + rep * 128;
        const float* prow = projw + (size_t)f * DIM + h * CH;
        float4 w[6];
#pragma unroll
        for (int jj = 0; jj < 6; jj++) w[jj] = make_float4(0.f, 0.f, 0.f, 0.f);
        for (int c = 0; c < CH; c++) {
            float pf = prow[c];
            const float* srow = S + c * 52 + dh;
#pragma unroll
            for (int jj = 0; jj < 6; jj++) {
                float4 s = *(const float4*)(srow + 4 * jj);
                w[jj].x += pf * s.x; w[jj].y += pf * s.y;
                w[jj].z += pf * s.z; w[jj].w += pf * s.w;
            }
        }
        size_t off = ((size_t)b * DIM + f) * DIM + h * CH + dh;
        uint32_t* wh = (uint32_t*)(g_wh + off);
        uint32_t* wl = (uint32_t*)(g_wl + off);
#pragma unroll
        for (int jj = 0; jj < 6; jj++) {
            uint32_t h0, l0, h1, l1;
            bsplit2(w[jj].x, w[jj].y, h0, l0);
            bsplit2(w[jj].z, w[jj].w, h1, l1);
            wh[2*jj] = h0; wh[2*jj+1] = h1;
            wl[2*jj] = l0; wl[2*jj+1] = l1;
        }
    }
}

// ---------------------------------------------------------------------------
extern "C" void kernel_launch(void* const* d_in, const int* in_sizes, int n_in,
                              void* d_out, int out_size)
{
    const float* x      = (const float*)d_in[0];
    const float* qkv_w  = (const float*)d_in[1];
    const float* temp   = (const float*)d_in[2];
    const float* proj_w = (const float*)d_in[3];
    const float* proj_b = (const float*)d_in[4];
    float* out = (float*)d_out;

    void *xh, *xl, *wqh, *wql;
    cudaGetSymbolAddress(&xh,  g_xh);
    cudaGetSymbolAddress(&xl,  g_xl);
    cudaGetSymbolAddress(&wqh, g_wqh);
    cudaGetSymbolAddress(&wql, g_wql);

    // 0) split x and qkv_w into bf16 h/l
    {
        int n4x = MTOT * KD / 4;
        split_kernel<<<(n4x + 255) / 256, 256>>>((const float4*)x, (uint2*)xh, (uint2*)xl, n4x);
        int n4w = ETOT * KD / 4;
        split_kernel<<<(n4w + 255) / 256, 256>>>((const float4*)qkv_w, (uint2*)wqh, (uint2*)wql, n4w);
    }

    cudaFuncSetAttribute(gemm_qkv_kernel,  cudaFuncAttributeMaxDynamicSharedMemorySize, GSMEM);
    cudaFuncSetAttribute(gemm_proj_kernel, cudaFuncAttributeMaxDynamicSharedMemorySize, GSMEM);
    cudaFuncSetAttribute(attn_mma_kernel,  cudaFuncAttributeMaxDynamicSharedMemorySize, ASMEM);

    // 1) qkv GEMM (e fastest for x-tile L2 reuse)
    gemm_qkv_kernel<<<dim3(ETOT / 128, MTOT / 128), 256, GSMEM>>>();

    // 2) attention: tensor-core partial S + norms, then combine
    attn_mma_kernel<<<512, 256, ASMEM>>>();
    attn_combine_kernel<<<256, 256>>>(temp, proj_w);

    // 3) proj GEMM per batch
    gemm_proj_kernel<<<dim3(DIM / 128, (NTOK + 127) / 128, BATCH), 256, GSMEM>>>(proj_b, out);
}

// round 15
// speedup vs baseline: 1.3738x; 1.3738x over previous
#include <cuda_runtime.h>
#include <cuda_fp16.h>
#include <math.h>
#include <cstdint>

#define BATCH 32
#define NTOK  3136
#define DIM   384
#define HEADS 8
#define CH    48
#define MTOT  (BATCH * NTOK)   // 100352
#define ETOT  (3 * DIM)        // 1152
#define KD    384

// Scratch (__device__ globals)
__device__ __half g_x16[(size_t)MTOT * KD];                   // x fp16 (single plane)
__device__ __half g_wqh[(size_t)ETOT * KD];                   // qkv_w fp16 high
__device__ __half g_wql[(size_t)ETOT * KD];                   // qkv_w fp16 low
__device__ __half g_qkh[((size_t)2 * DIM + 16) * MTOT];       // q,k fp16 high [e][m]
__device__ __half g_qkl[((size_t)2 * DIM + 16) * MTOT];       // low
__device__ __half g_vt [((size_t)MTOT + 128) * KD];           // v^T [m][d] fp16 single
__device__ __half g_wbh[(size_t)BATCH * DIM * DIM];           // W_b=P·S [b][f][d] high
__device__ __half g_wbl[(size_t)BATCH * DIM * DIM];           // low
__device__ float  g_ps [512 * 48 * 48];                       // partial S
__device__ float  g_pn [512 * 96];                            // partial sq-norms

// ---------------------------------------------------------------------------
__device__ __forceinline__ uint32_t smem_u32(const void* p) {
    uint32_t a;
    asm("{ .reg .u64 t; cvta.to.shared.u64 t, %1; cvt.u32.u64 %0, t; }" : "=r"(a) : "l"(p));
    return a;
}
__device__ __forceinline__ void hsplit2(float x0, float x1, uint32_t& h, uint32_t& l) {
    __half h0 = __float2half_rn(x0);
    __half h1 = __float2half_rn(x1);
    __half l0 = __float2half_rn(x0 - __half2float(h0));
    __half l1 = __float2half_rn(x1 - __half2float(h1));
    __half2 hv = __halves2half2(h0, h1);
    __half2 lv = __halves2half2(l0, l1);
    h = *reinterpret_cast<uint32_t*>(&hv);
    l = *reinterpret_cast<uint32_t*>(&lv);
}
__device__ __forceinline__ void cp16(uint32_t d, const void* s) {
    asm volatile("cp.async.cg.shared.global [%0], [%1], 16;" :: "r"(d), "l"(s));
}
__device__ __forceinline__ void cp_commit() { asm volatile("cp.async.commit_group;"); }

#define LDSM4(r0, r1, r2, r3, addr) \
    asm volatile("ldmatrix.sync.aligned.m8n8.x4.shared.b16 {%0,%1,%2,%3}, [%4];" \
        : "=r"(r0), "=r"(r1), "=r"(r2), "=r"(r3) : "r"(addr))

#define MMA_F16(d, A0,A1,A2,A3, B0,B1) \
    asm volatile("mma.sync.aligned.m16n8k16.row.col.f32.f16.f16.f32 " \
        "{%0,%1,%2,%3}, {%4,%5,%6,%7}, {%8,%9}, {%0,%1,%2,%3};" \
        : "+f"((d)[0]), "+f"((d)[1]), "+f"((d)[2]), "+f"((d)[3]) \
        : "r"(A0), "r"(A1), "r"(A2), "r"(A3), "r"(B0), "r"(B1))

// ---------------------------------------------------------------------------
// 2-term fp16 GEMM machinery: tile 128x128, K=384 in 12 chunks of 32.
// Stage = 3 planes of 128 rows x 32 halves (stride 40 halves = 80 B).
// MODE 0: plane0=Ah, plane1=Al, plane2=B      (C = Ah·B + Al·B; B rounded)
// MODE 1: plane0=A,  plane1=Bh, plane2=Bl     (C = A·Bh + A·Bl; A rounded)
// 3-stage cp.async pipeline, one __syncthreads per chunk.
// ---------------------------------------------------------------------------
#define PL     10240                 // bytes per plane (128 * 80)
#define STG    (3 * PL)              // 30720 per stage
#define GSMEM3 (3 * STG)             // 92160 (3 stages)

__device__ __forceinline__ void load_stage3(
    uint32_t sb, const __half* p0, const __half* p1, const __half* p2, int k0, int tid)
{
    const int row = tid >> 1;
    const int s2  = (tid & 1) * 2;
    const uint32_t ro = row * 80 + s2 * 16;
    const size_t go = (size_t)row * KD + k0 + s2 * 8;
    cp16(sb + ro,          p0 + go);  cp16(sb + ro + 16,          p0 + go + 8);
    cp16(sb + PL + ro,     p1 + go);  cp16(sb + PL + ro + 16,     p1 + go + 8);
    cp16(sb + 2*PL + ro,   p2 + go);  cp16(sb + 2*PL + ro + 16,   p2 + go + 8);
}

template<int MODE>
__device__ __forceinline__ void mma_stage3(
    uint32_t ss, int wm, int wn, int lane, float acc[4][4][4])
{
    const int j  = lane >> 3;
    const int rr = lane & 7;
#pragma unroll
    for (int kk = 0; kk < 32; kk += 16) {
        uint32_t b0f[4][2], b1f[4][2];
#pragma unroll
        for (int p = 0; p < 2; p++) {
            uint32_t off = (uint32_t)(((wn + (2*p + (j >> 1)) * 8 + rr) * 40 + kk + (j & 1) * 8) * 2);
            if (MODE == 0) {
                LDSM4(b0f[2*p][0], b0f[2*p][1], b0f[2*p+1][0], b0f[2*p+1][1], ss + 2*PL + off);
            } else {
                LDSM4(b0f[2*p][0], b0f[2*p][1], b0f[2*p+1][0], b0f[2*p+1][1], ss + PL + off);
                LDSM4(b1f[2*p][0], b1f[2*p][1], b1f[2*p+1][0], b1f[2*p+1][1], ss + 2*PL + off);
            }
        }
#pragma unroll
        for (int mt = 0; mt < 4; mt++) {
            uint32_t aoff = (uint32_t)(((wm + mt*16 + (j & 1) * 8 + rr) * 40 + kk + (j >> 1) * 8) * 2);
            uint32_t a0, a1, a2, a3, l0, l1, l2, l3;
            LDSM4(a0, a1, a2, a3, ss + aoff);
            if (MODE == 0) LDSM4(l0, l1, l2, l3, ss + PL + aoff);
#pragma unroll
            for (int nt = 0; nt < 4; nt++) {
                if (MODE == 0) {
                    MMA_F16(acc[mt][nt], a0, a1, a2, a3, b0f[nt][0], b0f[nt][1]);
                    MMA_F16(acc[mt][nt], l0, l1, l2, l3, b0f[nt][0], b0f[nt][1]);
                } else {
                    MMA_F16(acc[mt][nt], a0, a1, a2, a3, b0f[nt][0], b0f[nt][1]);
                    MMA_F16(acc[mt][nt], a0, a1, a2, a3, b1f[nt][0], b1f[nt][1]);
                }
            }
        }
    }
}

template<int MODE>
__device__ __forceinline__ void gemm_mainloop3(
    uint32_t sbase, const __half* p0, const __half* p1, const __half* p2,
    int wm, int wn, int lane, int tid, float acc[4][4][4])
{
    load_stage3(sbase,       p0, p1, p2, 0,  tid); cp_commit();
    load_stage3(sbase + STG, p0, p1, p2, 32, tid); cp_commit();
    for (int c = 0; c < 12; c++) {
        if (c < 11) { asm volatile("cp.async.wait_group 1;"); }
        else        { asm volatile("cp.async.wait_group 0;"); }
        __syncthreads();
        if (c + 2 < 12) {
            load_stage3(sbase + ((c + 2) % 3) * STG, p0, p1, p2, (c + 2) * 32, tid);
            cp_commit();
        }
        mma_stage3<MODE>(sbase + (c % 3) * STG, wm, wn, lane, acc);
    }
}

// ---------------------------------------------------------------------------
// Prepasses
// ---------------------------------------------------------------------------
__global__ void __launch_bounds__(256) split_hl_kernel(
    const float4* __restrict__ src, uint2* __restrict__ dh, uint2* __restrict__ dl, int n4)
{
    int i = blockIdx.x * 256 + threadIdx.x;
    if (i >= n4) return;
    float4 v = src[i];
    uint32_t h0, l0, h1, l1;
    hsplit2(v.x, v.y, h0, l0);
    hsplit2(v.z, v.w, h1, l1);
    dh[i] = make_uint2(h0, h1);
    dl[i] = make_uint2(l0, l1);
}

__global__ void __launch_bounds__(256) cvt_f16_kernel(
    const float4* __restrict__ src, uint2* __restrict__ dst, int n4)
{
    int i = blockIdx.x * 256 + threadIdx.x;
    if (i >= n4) return;
    float4 v = src[i];
    __half2 a = __floats2half2_rn(v.x, v.y);
    __half2 b = __floats2half2_rn(v.z, v.w);
    dst[i] = make_uint2(*(uint32_t*)&a, *(uint32_t*)&b);
}

// ---------------------------------------------------------------------------
// G1: qkv GEMM (MODE 0: A = weights h/l, B = x single).
// q/k -> fp16 h/l [e][m]; v -> transposed fp16 single [m][d].
// ---------------------------------------------------------------------------
__global__ void __launch_bounds__(256, 2) gemm_qkv_kernel()
{
    extern __shared__ char sb[];
    const uint32_t sbase = smem_u32(sb);
    const int tid  = threadIdx.x;
    const int wid  = tid >> 5;
    const int lane = tid & 31;
    const int g = lane >> 2, t = lane & 3;
    const int a0 = blockIdx.x * 128;   // e (fastest -> x-tile L2 reuse)
    const int b0 = blockIdx.y * 128;   // m
    const int wm = (wid >> 2) * 64, wn = (wid & 3) * 32;

    float acc[4][4][4];
#pragma unroll
    for (int mt = 0; mt < 4; mt++)
#pragma unroll
        for (int nt = 0; nt < 4; nt++)
#pragma unroll
            for (int i = 0; i < 4; i++) acc[mt][nt][i] = 0.f;

    gemm_mainloop3<0>(sbase,
                      g_wqh + (size_t)a0 * KD, g_wql + (size_t)a0 * KD,
                      g_x16 + (size_t)b0 * KD,
                      wm, wn, lane, tid, acc);

    if (a0 < 2 * DIM) {
        // q/k: fp16 h/l [e][m]
#pragma unroll
        for (int mt = 0; mt < 4; mt++) {
            int row = a0 + wm + mt * 16 + g;
#pragma unroll
            for (int nt = 0; nt < 4; nt++) {
                int col = b0 + wn + nt * 8 + 2 * t;
                uint32_t hw, lw;
                hsplit2(acc[mt][nt][0], acc[mt][nt][1], hw, lw);
                *(uint32_t*)(g_qkh + (size_t)row * MTOT + col) = hw;
                *(uint32_t*)(g_qkl + (size_t)row * MTOT + col) = lw;
                hsplit2(acc[mt][nt][2], acc[mt][nt][3], hw, lw);
                *(uint32_t*)(g_qkh + (size_t)(row + 8) * MTOT + col) = hw;
                *(uint32_t*)(g_qkl + (size_t)(row + 8) * MTOT + col) = lw;
            }
        }
    } else {
        // v: transpose-stage then fp16 single [m][d]
        __syncthreads();
        float* smf = (float*)sb;  // [128 m][132 e]
#pragma unroll
        for (int mt = 0; mt < 4; mt++) {
            int er = wm + mt * 16 + g;
#pragma unroll
            for (int nt = 0; nt < 4; nt++) {
                int mc = wn + nt * 8 + 2 * t;
                smf[mc * 132 + er]           = acc[mt][nt][0];
                smf[(mc + 1) * 132 + er]     = acc[mt][nt][1];
                smf[mc * 132 + er + 8]       = acc[mt][nt][2];
                smf[(mc + 1) * 132 + er + 8] = acc[mt][nt][3];
            }
        }
        __syncthreads();
        const int mrow = tid >> 1, hf = tid & 1;
        const int dv0 = a0 - 2 * DIM;
        const float* srow = smf + mrow * 132 + hf * 64;
        uint32_t* tv = (uint32_t*)(g_vt + (size_t)(b0 + mrow) * KD + dv0 + hf * 64);
#pragma unroll
        for (int jj = 0; jj < 32; jj++) {
            __half2 p = __floats2half2_rn(srow[2 * jj], srow[2 * jj + 1]);
            tv[jj] = *(uint32_t*)&p;
        }
    }
}

// ---------------------------------------------------------------------------
// G2: proj GEMM per batch (MODE 1: A = v^T single, B = W_b h/l).
// ---------------------------------------------------------------------------
__global__ void __launch_bounds__(256, 2) gemm_proj_kernel(
    const float* __restrict__ bias, float* __restrict__ out)
{
    extern __shared__ char sb[];
    const uint32_t sbase = smem_u32(sb);
    const int tid  = threadIdx.x;
    const int wid  = tid >> 5;
    const int lane = tid & 31;
    const int g = lane >> 2, t = lane & 3;
    const int f0 = blockIdx.x * 128;
    const int n0 = blockIdx.y * 128;
    const int b  = blockIdx.z;
    const int wm = (wid >> 2) * 64, wn = (wid & 3) * 32;
    const size_t vrow0 = (size_t)b * NTOK + n0;
    const size_t wrow0 = (size_t)b * DIM + f0;
    const int nlim = NTOK - n0;

    float acc[4][4][4];
#pragma unroll
    for (int mt = 0; mt < 4; mt++)
#pragma unroll
        for (int nt = 0; nt < 4; nt++)
#pragma unroll
            for (int i = 0; i < 4; i++) acc[mt][nt][i] = 0.f;

    gemm_mainloop3<1>(sbase,
                      g_vt  + vrow0 * KD,
                      g_wbh + wrow0 * KD, g_wbl + wrow0 * KD,
                      wm, wn, lane, tid, acc);

#pragma unroll
    for (int mt = 0; mt < 4; mt++) {
        int nrow = wm + mt * 16 + g;
#pragma unroll
        for (int nt = 0; nt < 4; nt++) {
            int col = f0 + wn + nt * 8 + 2 * t;
            float bv0 = bias[col], bv1 = bias[col + 1];
            if (nrow < nlim)
                *(float2*)(out + ((size_t)b * NTOK + n0 + nrow) * DIM + col) =
                    make_float2(acc[mt][nt][0] + bv0, acc[mt][nt][1] + bv1);
            if (nrow + 8 < nlim)
                *(float2*)(out + ((size_t)b * NTOK + n0 + nrow + 8) * DIM + col) =
                    make_float2(acc[mt][nt][2] + bv0, acc[mt][nt][3] + bv1);
        }
    }
}

// ---------------------------------------------------------------------------
// attn partial: per (b,h,half) 3-term fp16 S(48x48 in 64x64) + sq-norms.
// planes: qh | ql | kh | kl
// ---------------------------------------------------------------------------
#define APLANE 5120                   // 64 rows * 80 B
#define ASTAGE (4 * APLANE)
#define ASMEM  (2 * ASTAGE)           // 40960

__global__ void __launch_bounds__(256, 2) attn_mma_kernel()
{
    extern __shared__ char sb[];
    const uint32_t sbase = smem_u32(sb);
    const int blk = blockIdx.x;           // 0..511
    const int bh = blk >> 1, half = blk & 1;
    const int b = bh >> 3, h = bh & 7;
    const int tid  = threadIdx.x;
    const int wid  = tid >> 5;
    const int lane = tid & 31;
    const int g = lane >> 2, t = lane & 3;
    const int j = lane >> 3, rr = lane & 7;
    const int wm = (wid >> 1) * 16;
    const int wn = (wid & 1) * 32;

    const size_t bcol = (size_t)b * NTOK + half * 1568;
    const size_t qoff = (size_t)(h * CH) * MTOT + bcol;
    const size_t koff = (size_t)(DIM + h * CH) * MTOT + bcol;

    const int lrow = tid & 63;
    const int pl   = tid >> 6;
    const __half* myrow;
    {
        const __half* bases[4] = { g_qkh + qoff, g_qkl + qoff, g_qkh + koff, g_qkl + koff };
        myrow = bases[pl] + (size_t)lrow * MTOT;
    }

    float acc[4][4];
#pragma unroll
    for (int nt = 0; nt < 4; nt++)
#pragma unroll
        for (int i = 0; i < 4; i++) acc[nt][i] = 0.f;
    float nacc = 0.f;

    const int nr_row = (tid < 48) ? tid : tid - 48;
    const int nr_pl  = (tid < 48) ? 0 : 2;

    {
        const uint32_t d0 = sbase + pl * APLANE + lrow * 80;
        const __half* s0 = myrow;
        cp16(d0, s0); cp16(d0 + 16, s0 + 8); cp16(d0 + 32, s0 + 16); cp16(d0 + 48, s0 + 24);
        cp_commit();
    }
    for (int c = 0; c < 49; c++) {
        if (c < 48) {
            const uint32_t d0 = sbase + ((c + 1) & 1) * ASTAGE + pl * APLANE + lrow * 80;
            const __half* s0 = myrow + (c + 1) * 32;
            cp16(d0, s0); cp16(d0 + 16, s0 + 8); cp16(d0 + 32, s0 + 16); cp16(d0 + 48, s0 + 24);
            cp_commit();
            asm volatile("cp.async.wait_group 1;");
        } else {
            asm volatile("cp.async.wait_group 0;");
        }
        __syncthreads();
        const uint32_t ss = sbase + (c & 1) * ASTAGE;
        if (tid < 96) {
            const char* ph  = sb + (c & 1) * ASTAGE + nr_pl * APLANE + nr_row * 80;
            const char* plo = ph + APLANE;
#pragma unroll
            for (int i = 0; i < 16; i++) {
                __half2 hv = *(const __half2*)(ph + 4 * i);
                __half2 lv = *(const __half2*)(plo + 4 * i);
                float2 hf = __half22float2(hv);
                float2 lf = __half22float2(lv);
                float v0 = hf.x + lf.x, v1 = hf.y + lf.y;
                nacc += v0 * v0 + v1 * v1;
            }
        }
#pragma unroll
        for (int kk = 0; kk < 32; kk += 16) {
            uint32_t bh2[4][2], bl2[4][2];
#pragma unroll
            for (int p = 0; p < 2; p++) {
                uint32_t off = (uint32_t)(((wn + (2*p + (j >> 1)) * 8 + rr) * 40 + kk + (j & 1) * 8) * 2);
                LDSM4(bh2[2*p][0], bh2[2*p][1], bh2[2*p+1][0], bh2[2*p+1][1], ss + 2*APLANE + off);
                LDSM4(bl2[2*p][0], bl2[2*p][1], bl2[2*p+1][0], bl2[2*p+1][1], ss + 3*APLANE + off);
            }
            uint32_t aoff = (uint32_t)(((wm + (j & 1) * 8 + rr) * 40 + kk + (j >> 1) * 8) * 2);
            uint32_t a0r, a1r, a2r, a3r, l0r, l1r, l2r, l3r;
            LDSM4(a0r, a1r, a2r, a3r, ss + aoff);
            LDSM4(l0r, l1r, l2r, l3r, ss + APLANE + aoff);
#pragma unroll
            for (int nt = 0; nt < 4; nt++) {
                MMA_F16(acc[nt], a0r, a1r, a2r, a3r, bh2[nt][0], bh2[nt][1]);
                MMA_F16(acc[nt], l0r, l1r, l2r, l3r, bh2[nt][0], bh2[nt][1]);
                MMA_F16(acc[nt], a0r, a1r, a2r, a3r, bl2[nt][0], bl2[nt][1]);
            }
        }
        __syncthreads();
    }

    float* ps = g_ps + (size_t)blk * 2304;
    const int c0 = wm + g;
#pragma unroll
    for (int nt = 0; nt < 4; nt++) {
        int d0 = wn + nt * 8 + 2 * t;
        if (d0 < 48) {
            if (c0 < 48) {
                ps[c0 * 48 + d0]     = acc[nt][0];
                ps[c0 * 48 + d0 + 1] = acc[nt][1];
            }
            if (c0 + 8 < 48) {
                ps[(c0 + 8) * 48 + d0]     = acc[nt][2];
                ps[(c0 + 8) * 48 + d0 + 1] = acc[nt][3];
            }
        }
    }
    if (tid < 96) g_pn[blk * 96 + tid] = nacc;
}

// ---------------------------------------------------------------------------
// attn combine: sum partials, normalize, temp, softmax, W_b = P·S -> fp16 h/l
// ---------------------------------------------------------------------------
__global__ void __launch_bounds__(256) attn_combine_kernel(
    const float* __restrict__ temperature, const float* __restrict__ projw)
{
    __shared__ float S[48 * 52];
    __shared__ float norms[96];

    const int bh = blockIdx.x;
    const int b = bh >> 3, h = bh & 7;
    const int tid = threadIdx.x;

    const float* ps0 = g_ps + (size_t)(bh * 2) * 2304;
    const float* ps1 = ps0 + 2304;
    for (int c = tid; c < 2304; c += 256)
        S[(c / 48) * 52 + (c % 48)] = ps0[c] + ps1[c];
    if (tid < 96) {
        float n = g_pn[(bh * 2) * 96 + tid] + g_pn[(bh * 2 + 1) * 96 + tid];
        norms[tid] = 1.f / fmaxf(sqrtf(n), 1e-12f);
    }
    __syncthreads();

    const float temp = temperature[h];
    for (int c = tid; c < 2304; c += 256) {
        int i = c / 48, jj = c % 48;
        S[i * 52 + jj] *= norms[i] * norms[48 + jj] * temp;
    }
    __syncthreads();

    if (tid < CH) {
        float* row = S + tid * 52;
        float mx = -1e30f;
#pragma unroll
        for (int d = 0; d < CH; d++) mx = fmaxf(mx, row[d]);
        float s = 0.f;
#pragma unroll
        for (int d = 0; d < CH; d++) { float e = expf(row[d] - mx); row[d] = e; s += e; }
        float inv = 1.f / s;
#pragma unroll
        for (int d = 0; d < CH; d++) row[d] *= inv;
    }
    __syncthreads();

    const int fl = tid >> 1;
    const int dh = (tid & 1) * 24;
    for (int rep = 0; rep < 3; rep++) {
        int f = fl + rep * 128;
        const float* prow = projw + (size_t)f * DIM + h * CH;
        float4 w[6];
#pragma unroll
        for (int jj = 0; jj < 6; jj++) w[jj] = make_float4(0.f, 0.f, 0.f, 0.f);
        for (int c = 0; c < CH; c++) {
            float pf = prow[c];
            const float* srow = S + c * 52 + dh;
#pragma unroll
            for (int jj = 0; jj < 6; jj++) {
                float4 s = *(const float4*)(srow + 4 * jj);
                w[jj].x += pf * s.x; w[jj].y += pf * s.y;
                w[jj].z += pf * s.z; w[jj].w += pf * s.w;
            }
        }
        size_t off = ((size_t)b * DIM + f) * DIM + h * CH + dh;
        uint32_t* wh = (uint32_t*)(g_wbh + off);
        uint32_t* wl = (uint32_t*)(g_wbl + off);
#pragma unroll
        for (int jj = 0; jj < 6; jj++) {
            uint32_t h0, l0, h1, l1;
            hsplit2(w[jj].x, w[jj].y, h0, l0);
            hsplit2(w[jj].z, w[jj].w, h1, l1);
            wh[2*jj] = h0; wh[2*jj+1] = h1;
            wl[2*jj] = l0; wl[2*jj+1] = l1;
        }
    }
}

// ---------------------------------------------------------------------------
extern "C" void kernel_launch(void* const* d_in, const int* in_sizes, int n_in,
                              void* d_out, int out_size)
{
    const float* x      = (const float*)d_in[0];
    const float* qkv_w  = (const float*)d_in[1];
    const float* temp   = (const float*)d_in[2];
    const float* proj_w = (const float*)d_in[3];
    const float* proj_b = (const float*)d_in[4];
    float* out = (float*)d_out;

    void *x16, *wqh, *wql;
    cudaGetSymbolAddress(&x16, g_x16);
    cudaGetSymbolAddress(&wqh, g_wqh);
    cudaGetSymbolAddress(&wql, g_wql);

    // 0) prepass: x -> fp16 single; qkv_w -> fp16 h/l
    {
        int n4x = MTOT * KD / 4;
        cvt_f16_kernel<<<(n4x + 255) / 256, 256>>>((const float4*)x, (uint2*)x16, n4x);
        int n4w = ETOT * KD / 4;
        split_hl_kernel<<<(n4w + 255) / 256, 256>>>((const float4*)qkv_w, (uint2*)wqh, (uint2*)wql, n4w);
    }

    cudaFuncSetAttribute(gemm_qkv_kernel,  cudaFuncAttributeMaxDynamicSharedMemorySize, GSMEM3);
    cudaFuncSetAttribute(gemm_proj_kernel, cudaFuncAttributeMaxDynamicSharedMemorySize, GSMEM3);
    cudaFuncSetAttribute(attn_mma_kernel,  cudaFuncAttributeMaxDynamicSharedMemorySize, ASMEM);

    // 1) qkv GEMM (2-term fp16, 3-stage pipeline)
    gemm_qkv_kernel<<<dim3(ETOT / 128, MTOT / 128), 256, GSMEM3>>>();

    // 2) attention: 3-term fp16 partial S + norms, then combine -> W_b fp16 h/l
    attn_mma_kernel<<<512, 256, ASMEM>>>();
    attn_combine_kernel<<<256, 256>>>(temp, proj_w);

    // 3) proj GEMM per batch (2-term fp16)
    gemm_proj_kernel<<<dim3(DIM / 128, (NTOK + 127) / 128, BATCH), 256, GSMEM3>>>(proj_b, out);
}